// round 3
// baseline (speedup 1.0000x reference)
#include <cuda_runtime.h>
#include <math.h>

// Problem constants (shapes fixed by the reference)
#define NMAX 30000
#define EMAX 480000
#define TEMAX (EMAX + NMAX)
#define FMAXD 512

// ------------------------- device scratch (static; no allocs) ----------------
__device__ __align__(16) float g_h[(size_t)NMAX * FMAXD];   // GEMM output
__device__ __align__(16) float g_f[(size_t)NMAX * FMAXD];   // aggregated features
__device__ float g_asrc[NMAX * 4];
__device__ float g_adst[NMAX * 4];
__device__ int   g_deg[NMAX];
__device__ int   g_off[NMAX + 1];
__device__ int   g_cur[NMAX];
__device__ int   g_esrc[TEMAX];

// ------------------------- CSC build ----------------------------------------
__global__ void deg_init(int N) {
    int i = blockIdx.x * blockDim.x + threadIdx.x;
    if (i < N) g_deg[i] = 1;  // self loop
}

// edge_index is int32 on the wire (JAX x64 disabled): [2, E] row-major.
__global__ void deg_count(const int* __restrict__ ei, int E, int N) {
    int i = blockIdx.x * blockDim.x + threadIdx.x;
    if (i < E) {
        int d = ei[E + i];
        if (d >= 0 && d < N) atomicAdd(&g_deg[d], 1);
    }
}

__global__ void scan1024(int N) {
    __shared__ int sp[1024];
    int t = threadIdx.x;
    int IT = (N + 1023) >> 10;
    int b = t * IT;
    int e = min(N, b + IT);
    int s = 0;
    for (int i = b; i < e; i++) s += g_deg[i];
    sp[t] = s;
    __syncthreads();
    for (int off = 1; off < 1024; off <<= 1) {
        int v = (t >= off) ? sp[t - off] : 0;
        __syncthreads();
        sp[t] += v;
        __syncthreads();
    }
    int run = (t == 0) ? 0 : sp[t - 1];
    for (int i = b; i < e; i++) {
        g_off[i] = run;
        g_cur[i] = run;
        run += g_deg[i];
    }
    if (t == 1023) g_off[N] = sp[1023];
}

__global__ void fill_csc(const int* __restrict__ ei, int E, int N) {
    int i = blockIdx.x * blockDim.x + threadIdx.x;
    if (i >= E + N) return;
    int s, d;
    if (i < E) { s = ei[i]; d = ei[E + i]; }
    else       { s = i - E; d = s; }
    if (s < 0 || s >= N || d < 0 || d >= N) return;
    int pos = atomicAdd(&g_cur[d], 1);
    if (pos >= 0 && pos < TEMAX) g_esrc[pos] = s;
}

// ------------------------- SGEMM 128x128x8, 8x8 per thread -------------------
// C[M,N] = A[M,K] * B[K,N], row-major. C = g_h. A = (useF ? g_f : Aext).
__global__ void sgemm(const float* __restrict__ Aext, int useF,
                      const float* __restrict__ B, int M, int N, int K) {
    const float* A = useF ? (const float*)g_f : Aext;
    float* C = g_h;
    __shared__ float As[8][128];
    __shared__ float Bs[8][128];
    int t = threadIdx.x;
    int row0 = blockIdx.y * 128;
    int col0 = blockIdx.x * 128;

    int arow = t >> 1;          // 0..127
    int ak4  = (t & 1) * 4;     // 0 or 4
    int brow = t >> 5;          // 0..7
    int bcol4 = (t & 31) * 4;   // 0..124

    int tx = t & 15, ty = t >> 4;

    float acc[8][8];
#pragma unroll
    for (int i = 0; i < 8; i++)
#pragma unroll
        for (int j = 0; j < 8; j++) acc[i][j] = 0.f;

    for (int k0 = 0; k0 < K; k0 += 8) {
        float4 av;
        if (row0 + arow < M)
            av = *(const float4*)&A[(size_t)(row0 + arow) * K + k0 + ak4];
        else
            av = make_float4(0.f, 0.f, 0.f, 0.f);
        As[ak4 + 0][arow] = av.x;
        As[ak4 + 1][arow] = av.y;
        As[ak4 + 2][arow] = av.z;
        As[ak4 + 3][arow] = av.w;
        float4 bv = *(const float4*)&B[(size_t)(k0 + brow) * N + col0 + bcol4];
        *(float4*)&Bs[brow][bcol4] = bv;
        __syncthreads();
#pragma unroll
        for (int k = 0; k < 8; k++) {
            float ra[8], rb[8];
            *(float4*)&ra[0] = *(const float4*)&As[k][ty * 8];
            *(float4*)&ra[4] = *(const float4*)&As[k][ty * 8 + 4];
            *(float4*)&rb[0] = *(const float4*)&Bs[k][tx * 8];
            *(float4*)&rb[4] = *(const float4*)&Bs[k][tx * 8 + 4];
#pragma unroll
            for (int i = 0; i < 8; i++)
#pragma unroll
                for (int j = 0; j < 8; j++)
                    acc[i][j] += ra[i] * rb[j];
        }
        __syncthreads();
    }
#pragma unroll
    for (int i = 0; i < 8; i++) {
        int r = row0 + ty * 8 + i;
        if (r < M) {
            float4 v0 = make_float4(acc[i][0], acc[i][1], acc[i][2], acc[i][3]);
            float4 v1 = make_float4(acc[i][4], acc[i][5], acc[i][6], acc[i][7]);
            *(float4*)&C[(size_t)r * N + col0 + tx * 8] = v0;
            *(float4*)&C[(size_t)r * N + col0 + tx * 8 + 4] = v1;
        }
    }
}

// ------------------------- attention coefficients ----------------------------
// One warp per (node, head): a_src[n,h] = <h[n,h,:], att_src[h,:]>, same for dst.
// Reads g_h.
__global__ void attn_coef(const float* __restrict__ at_s,
                          const float* __restrict__ at_d,
                          int N, int H) {
    const int C = 128;
    int gw = (blockIdx.x * blockDim.x + threadIdx.x) >> 5;
    int lane = threadIdx.x & 31;
    if (gw >= N * H) return;
    int n = gw / H, hh = gw - n * H;
    const float* hp = g_h + (size_t)n * H * C + (size_t)hh * C;
    float s1 = 0.f, s2 = 0.f;
    for (int c = lane; c < C; c += 32) {
        float v = hp[c];
        s1 += v * at_s[hh * C + c];
        s2 += v * at_d[hh * C + c];
    }
#pragma unroll
    for (int o = 16; o; o >>= 1) {
        s1 += __shfl_xor_sync(0xffffffffu, s1, o);
        s2 += __shfl_xor_sync(0xffffffffu, s2, o);
    }
    if (lane == 0) {
        g_asrc[n * H + hh] = s1;
        g_adst[n * H + hh] = s2;
    }
}

// ------------------------- fused softmax + aggregate -------------------------
// One 128-thread CTA per dst node. Thread t owns channel t of every head.
// Reads g_h; writes g_f (writeOut==0) or outp (writeOut==1).
template <int H>
__global__ void aggregate(const float* __restrict__ bias,
                          float* __restrict__ outp, int writeOut, int doRelu) {
    const int C = 128;
    int n = blockIdx.x;
    int t = threadIdx.x;
    __shared__ int   ssrc[128];
    __shared__ float sw[H * 128];
    __shared__ float red[H * 128];

    const float* h = g_h;
    float* out = writeOut ? outp : (float*)g_f;

    int beg = g_off[n], end = g_off[n + 1];

    float adh[H];
#pragma unroll
    for (int hh = 0; hh < H; hh++) adh[hh] = g_adst[n * H + hh];

    // pass 1: segment max per head
    float mx[H];
#pragma unroll
    for (int hh = 0; hh < H; hh++) mx[hh] = -1e30f;
    for (int k = beg + t; k < end; k += 128) {
        int s = g_esrc[k];
#pragma unroll
        for (int hh = 0; hh < H; hh++) {
            float e = g_asrc[s * H + hh] + adh[hh];
            e = e > 0.f ? e : 0.2f * e;
            mx[hh] = fmaxf(mx[hh], e);
        }
    }
#pragma unroll
    for (int hh = 0; hh < H; hh++) red[hh * 128 + t] = mx[hh];
    __syncthreads();
    for (int st = 64; st; st >>= 1) {
        if (t < st) {
#pragma unroll
            for (int hh = 0; hh < H; hh++)
                red[hh * 128 + t] = fmaxf(red[hh * 128 + t], red[hh * 128 + t + st]);
        }
        __syncthreads();
    }
#pragma unroll
    for (int hh = 0; hh < H; hh++) mx[hh] = red[hh * 128];
    __syncthreads();

    // pass 2: exp-weights + accumulate
    float acc[H], den[H];
#pragma unroll
    for (int hh = 0; hh < H; hh++) { acc[hh] = 0.f; den[hh] = 0.f; }

    for (int base = beg; base < end; base += 128) {
        int k = base + t;
        if (k < end) {
            int s = g_esrc[k];
            ssrc[t] = s;
#pragma unroll
            for (int hh = 0; hh < H; hh++) {
                float e = g_asrc[s * H + hh] + adh[hh];
                e = e > 0.f ? e : 0.2f * e;
                float w = expf(e - mx[hh]);
                sw[hh * 128 + t] = w;
                den[hh] += w;
            }
        }
        __syncthreads();
        int cnt = min(128, end - base);
#pragma unroll 2
        for (int j = 0; j < cnt; j++) {
            int s = ssrc[j];
            const float* hp = h + (size_t)s * (H * C) + t;
#pragma unroll
            for (int hh = 0; hh < H; hh++)
                acc[hh] += sw[hh * 128 + j] * hp[hh * C];
        }
        __syncthreads();
    }

    // reduce denominators across threads
#pragma unroll
    for (int hh = 0; hh < H; hh++) red[hh * 128 + t] = den[hh];
    __syncthreads();
    for (int st = 64; st; st >>= 1) {
        if (t < st) {
#pragma unroll
            for (int hh = 0; hh < H; hh++)
                red[hh * 128 + t] += red[hh * 128 + t + st];
        }
        __syncthreads();
    }
#pragma unroll
    for (int hh = 0; hh < H; hh++) {
        float v = acc[hh] / red[hh * 128] + bias[hh * C + t];
        if (doRelu) v = fmaxf(v, 0.f);
        out[(size_t)n * (H * C) + hh * C + t] = v;
    }
}

// ------------------------- launch ---------------------------------------------
extern "C" void kernel_launch(void* const* d_in, const int* in_sizes, int n_in,
                              void* d_out, int out_size) {
    const float* x   = (const float*)d_in[0];
    const int*   ei  = (const int*)d_in[1];     // int32 edge_index [2, E]
    const float* W1  = (const float*)d_in[2];
    const float* as1 = (const float*)d_in[3];
    const float* ad1 = (const float*)d_in[4];
    const float* b1  = (const float*)d_in[5];
    const float* W2  = (const float*)d_in[6];
    const float* as2 = (const float*)d_in[7];
    const float* ad2 = (const float*)d_in[8];
    const float* b2  = (const float*)d_in[9];
    const float* W3  = (const float*)d_in[10];
    const float* as3 = (const float*)d_in[11];
    const float* ad3 = (const float*)d_in[12];
    const float* b3  = (const float*)d_in[13];
    float* out = (float*)d_out;

    int N = in_sizes[0] / 256;   // 30000
    int E = in_sizes[1] / 2;     // 480000

    // ---- CSC build (incoming edges grouped by dst, self-loops included) ----
    deg_init<<<(N + 255) / 256, 256>>>(N);
    deg_count<<<(E + 255) / 256, 256>>>(ei, E, N);
    scan1024<<<1, 1024>>>(N);
    fill_csc<<<(E + N + 255) / 256, 256>>>(ei, E, N);

    // ---- layer 1: 256 -> 4x128, relu ----
    {
        dim3 grid(512 / 128, (N + 127) / 128);
        sgemm<<<grid, 256>>>(x, 0, W1, N, 512, 256);
        attn_coef<<<(N * 4 + 7) / 8, 256>>>(as1, ad1, N, 4);
        aggregate<4><<<N, 128>>>(b1, nullptr, 0, 1);
    }
    // ---- layer 2: 512 -> 4x128, relu ----
    {
        dim3 grid(512 / 128, (N + 127) / 128);
        sgemm<<<grid, 256>>>(nullptr, 1, W2, N, 512, 512);
        attn_coef<<<(N * 4 + 7) / 8, 256>>>(as2, ad2, N, 4);
        aggregate<4><<<N, 128>>>(b2, nullptr, 0, 1);
    }
    // ---- layer 3: 512 -> 128 (1 head, concat=False == identity for H=1) ----
    {
        dim3 grid(128 / 128, (N + 127) / 128);
        sgemm<<<grid, 256>>>(nullptr, 1, W3, N, 128, 512);
        attn_coef<<<(N * 1 + 7) / 8, 256>>>(as3, ad3, N, 1);
        aggregate<1><<<N, 128>>>(b3, out, 1, 0);
    }
}

// round 5
// speedup vs baseline: 1.4093x; 1.4093x over previous
#include <cuda_runtime.h>
#include <cuda_bf16.h>
#include <math.h>
#include <stdint.h>

#define NMAX 30000
#define EMAX 480000
#define TEMAX (EMAX + NMAX)

// ------------------------- device scratch (static; no allocs) ----------------
__device__ __align__(16) float g_h[(size_t)NMAX * 512];
__device__ __align__(16) float g_f[(size_t)NMAX * 512];
__device__ __align__(16) __nv_bfloat16 g_ah[(size_t)NMAX * 512];
__device__ __align__(16) __nv_bfloat16 g_al[(size_t)NMAX * 512];
__device__ __align__(16) __nv_bfloat16 g_wh[512 * 512];
__device__ __align__(16) __nv_bfloat16 g_wl[512 * 512];
__device__ float g_asrc[NMAX * 4];
__device__ float g_adst[NMAX * 4];
__device__ int   g_deg[NMAX];
__device__ int   g_off[NMAX + 1];
__device__ int   g_cur[NMAX];
__device__ int   g_esrc[TEMAX];

#define SW128(o) ((o) ^ (((o) >> 3) & 0x70))

__device__ __forceinline__ uint32_t smem_u32(const void* p) {
    uint32_t a;
    asm("{ .reg .u64 t; cvta.to.shared.u64 t, %1; cvt.u32.u64 %0, t; }" : "=r"(a) : "l"(p));
    return a;
}
__device__ __forceinline__ void ldm_x4(uint32_t* r, uint32_t addr) {
    asm volatile("ldmatrix.sync.aligned.m8n8.x4.shared.b16 {%0,%1,%2,%3}, [%4];"
                 : "=r"(r[0]), "=r"(r[1]), "=r"(r[2]), "=r"(r[3]) : "r"(addr));
}
__device__ __forceinline__ void mma16816(float* d, const uint32_t* a, const uint32_t* b) {
    asm volatile(
        "mma.sync.aligned.m16n8k16.row.col.f32.bf16.bf16.f32 "
        "{%0,%1,%2,%3}, {%4,%5,%6,%7}, {%8,%9}, {%0,%1,%2,%3};"
        : "+f"(d[0]), "+f"(d[1]), "+f"(d[2]), "+f"(d[3])
        : "r"(a[0]), "r"(a[1]), "r"(a[2]), "r"(a[3]), "r"(b[0]), "r"(b[1]));
}

// ------------------------- CSC build ----------------------------------------
__global__ void deg_init(int N) {
    int i = blockIdx.x * blockDim.x + threadIdx.x;
    if (i < N) g_deg[i] = 1;
}
__global__ void deg_count(const int* __restrict__ ei, int E, int N) {
    int i = blockIdx.x * blockDim.x + threadIdx.x;
    if (i < E) {
        int d = ei[E + i];
        if (d >= 0 && d < N) atomicAdd(&g_deg[d], 1);
    }
}
__global__ void scan1024(int N) {
    __shared__ int sp[1024];
    int t = threadIdx.x;
    int IT = (N + 1023) >> 10;
    int b = t * IT, e = min(N, b + IT);
    int s = 0;
    for (int i = b; i < e; i++) s += g_deg[i];
    sp[t] = s;
    __syncthreads();
    for (int off = 1; off < 1024; off <<= 1) {
        int v = (t >= off) ? sp[t - off] : 0;
        __syncthreads();
        sp[t] += v;
        __syncthreads();
    }
    int run = (t == 0) ? 0 : sp[t - 1];
    for (int i = b; i < e; i++) { g_off[i] = run; g_cur[i] = run; run += g_deg[i]; }
    if (t == 1023) g_off[N] = sp[1023];
}
__global__ void fill_csc(const int* __restrict__ ei, int E, int N) {
    int i = blockIdx.x * blockDim.x + threadIdx.x;
    if (i >= E + N) return;
    int s, d;
    if (i < E) { s = ei[i]; d = ei[E + i]; }
    else       { s = i - E; d = s; }
    if (s < 0 || s >= N || d < 0 || d >= N) return;
    int pos = atomicAdd(&g_cur[d], 1);
    if (pos >= 0 && pos < TEMAX) g_esrc[pos] = s;
}

// ------------------------- bf16 split / weight transpose ---------------------
__global__ void split_bf16(const float* __restrict__ in, int useF, int n) {
    int i = blockIdx.x * blockDim.x + threadIdx.x;
    if (i >= n) return;
    float v = useF ? g_f[i] : in[i];
    __nv_bfloat16 h = __float2bfloat16(v);
    g_ah[i] = h;
    g_al[i] = __float2bfloat16(v - __bfloat162float(h));
}
__global__ void wsplit(const float* __restrict__ W, int K, int N) {
    int i = blockIdx.x * blockDim.x + threadIdx.x;
    if (i >= K * N) return;
    int k = i / N, n = i - k * N;
    float v = W[i];
    __nv_bfloat16 h = __float2bfloat16(v);
    g_wh[(size_t)n * K + k] = h;
    g_wl[(size_t)n * K + k] = __float2bfloat16(v - __bfloat162float(h));
}

// ------------------------- HMMA bf16-split GEMM ------------------------------
// C[M,N] = A·W, A = g_ah+g_al [M,K] row-major, Wt = g_wh+g_wl [N,K] row-major.
// D = Ah·Bh + Ah·Bl + Al·Bh, fp32 register accumulation. C = g_h.
// CTA tile 128x128, 256 threads (8 warps: 4 in M x 2 in N, warp tile 32x64).
// K-chunk 64. SMEM: Ah|Al|Bh|Bl, each [128][64] bf16 SW128-swizzled (64 KB).
#define SA_H 0
#define SA_L 16384
#define SB_H 32768
#define SB_L 49152
#define SMTOT 65536

__global__ __launch_bounds__(256, 1) void hgemm(int M, int N, int K) {
    extern __shared__ char smem[];
    uint32_t sb = smem_u32(smem);
    int t = threadIdx.x, lane = t & 31, wid = t >> 5;
    int wm = (wid & 3) * 32;        // warp M offset in tile
    int wn = (wid >> 2) * 64;       // warp N offset in tile
    int row0 = blockIdx.y * 128, col0 = blockIdx.x * 128;

    float acc[2][8][4];
#pragma unroll
    for (int i = 0; i < 2; i++)
#pragma unroll
        for (int j = 0; j < 8; j++)
#pragma unroll
            for (int k = 0; k < 4; k++) acc[i][j][k] = 0.f;

    // gmem load mapping: 1024 uint4 per matrix, 256 threads -> 4 each
    int q = t & 7;        // 16B quad within row
    int rr = t >> 3;      // 0..31, rows rr, rr+32, rr+64, rr+96

    for (int k0 = 0; k0 < K; k0 += 64) {
#pragma unroll
        for (int j = 0; j < 4; j++) {
            int r = rr + j * 32;
            uint32_t off = SW128((uint32_t)(r * 128 + q * 16));
            int gr = row0 + r;
            uint4 vh = make_uint4(0, 0, 0, 0), vl = vh;
            if (gr < M) {
                vh = *(const uint4*)&g_ah[(size_t)gr * K + k0 + q * 8];
                vl = *(const uint4*)&g_al[(size_t)gr * K + k0 + q * 8];
            }
            *(uint4*)(smem + SA_H + off) = vh;
            *(uint4*)(smem + SA_L + off) = vl;
            int gn = col0 + r;  // grid.x * 128 == N always
            *(uint4*)(smem + SB_H + off) = *(const uint4*)&g_wh[(size_t)gn * K + k0 + q * 8];
            *(uint4*)(smem + SB_L + off) = *(const uint4*)&g_wl[(size_t)gn * K + k0 + q * 8];
        }
        __syncthreads();

#pragma unroll
        for (int ks = 0; ks < 4; ks++) {
            int kc = ks * 16;
            // A fragments: rows wm + mt*16 + (lane&15), col kc + (lane>>4)*8
            uint32_t ah[2][4], al[2][4];
#pragma unroll
            for (int mt = 0; mt < 2; mt++) {
                int r = wm + mt * 16 + (lane & 15);
                uint32_t off = SW128((uint32_t)(r * 128 + (kc + ((lane >> 4) << 3)) * 2));
                ldm_x4(ah[mt], sb + SA_H + off);
                ldm_x4(al[mt], sb + SA_L + off);
            }
            // B fragments: 4 pairs of n8-tiles
            uint32_t bh[4][4], bl[4][4];
#pragma unroll
            for (int p = 0; p < 4; p++) {
                int r = wn + p * 16 + ((lane >> 4) << 3) + (lane & 7);
                uint32_t off = SW128((uint32_t)(r * 128 + (kc + ((lane >> 3) & 1) * 8) * 2));
                ldm_x4(bh[p], sb + SB_H + off);
                ldm_x4(bl[p], sb + SB_L + off);
            }
#pragma unroll
            for (int mt = 0; mt < 2; mt++)
#pragma unroll
                for (int nt = 0; nt < 8; nt++) {
                    const uint32_t* bph = &bh[nt >> 1][(nt & 1) * 2];
                    const uint32_t* bpl = &bl[nt >> 1][(nt & 1) * 2];
                    mma16816(acc[mt][nt], ah[mt], bph);
                    mma16816(acc[mt][nt], ah[mt], bpl);
                    mma16816(acc[mt][nt], al[mt], bph);
                }
        }
        __syncthreads();
    }

    // epilogue: d0,d1 -> (row g, col c,c+1); d2,d3 -> row g+8
    int g = lane >> 2, cc = (lane & 3) * 2;
#pragma unroll
    for (int mt = 0; mt < 2; mt++) {
        int r0a = row0 + wm + mt * 16 + g;
#pragma unroll
        for (int nt = 0; nt < 8; nt++) {
            int c = col0 + wn + nt * 8 + cc;
            if (r0a < M)
                *(float2*)&g_h[(size_t)r0a * N + c] = make_float2(acc[mt][nt][0], acc[mt][nt][1]);
            if (r0a + 8 < M)
                *(float2*)&g_h[(size_t)(r0a + 8) * N + c] = make_float2(acc[mt][nt][2], acc[mt][nt][3]);
        }
    }
}

// ------------------------- attention coefficients ----------------------------
__global__ void attn_coef(const float* __restrict__ at_s,
                          const float* __restrict__ at_d, int N, int H) {
    const int C = 128;
    int gw = (blockIdx.x * blockDim.x + threadIdx.x) >> 5;
    int lane = threadIdx.x & 31;
    if (gw >= N * H) return;
    int n = gw / H, hh = gw - n * H;
    const float* hp = g_h + (size_t)n * H * C + (size_t)hh * C;
    float s1 = 0.f, s2 = 0.f;
    for (int c = lane; c < C; c += 32) {
        float v = hp[c];
        s1 += v * at_s[hh * C + c];
        s2 += v * at_d[hh * C + c];
    }
#pragma unroll
    for (int o = 16; o; o >>= 1) {
        s1 += __shfl_xor_sync(0xffffffffu, s1, o);
        s2 += __shfl_xor_sync(0xffffffffu, s2, o);
    }
    if (lane == 0) {
        g_asrc[n * H + hh] = s1;
        g_adst[n * H + hh] = s2;
    }
}

// ------------------------- fused softmax + aggregate -------------------------
template <int H>
__global__ void aggregate(const float* __restrict__ bias,
                          float* __restrict__ outp, int writeOut, int doRelu) {
    const int C = 128;
    int n = blockIdx.x;
    int t = threadIdx.x;
    __shared__ int   ssrc[128];
    __shared__ float sw[H * 128];
    __shared__ float red[H * 128];

    const float* h = g_h;
    float* out = writeOut ? outp : (float*)g_f;

    int beg = g_off[n], end = g_off[n + 1];

    float adh[H];
#pragma unroll
    for (int hh = 0; hh < H; hh++) adh[hh] = g_adst[n * H + hh];

    float mx[H];
#pragma unroll
    for (int hh = 0; hh < H; hh++) mx[hh] = -1e30f;
    for (int k = beg + t; k < end; k += 128) {
        int s = g_esrc[k];
#pragma unroll
        for (int hh = 0; hh < H; hh++) {
            float e = g_asrc[s * H + hh] + adh[hh];
            e = e > 0.f ? e : 0.2f * e;
            mx[hh] = fmaxf(mx[hh], e);
        }
    }
#pragma unroll
    for (int hh = 0; hh < H; hh++) red[hh * 128 + t] = mx[hh];
    __syncthreads();
    for (int st = 64; st; st >>= 1) {
        if (t < st) {
#pragma unroll
            for (int hh = 0; hh < H; hh++)
                red[hh * 128 + t] = fmaxf(red[hh * 128 + t], red[hh * 128 + t + st]);
        }
        __syncthreads();
    }
#pragma unroll
    for (int hh = 0; hh < H; hh++) mx[hh] = red[hh * 128];
    __syncthreads();

    float acc[H], den[H];
#pragma unroll
    for (int hh = 0; hh < H; hh++) { acc[hh] = 0.f; den[hh] = 0.f; }

    for (int base = beg; base < end; base += 128) {
        int k = base + t;
        if (k < end) {
            int s = g_esrc[k];
            ssrc[t] = s;
#pragma unroll
            for (int hh = 0; hh < H; hh++) {
                float e = g_asrc[s * H + hh] + adh[hh];
                e = e > 0.f ? e : 0.2f * e;
                float w = expf(e - mx[hh]);
                sw[hh * 128 + t] = w;
                den[hh] += w;
            }
        }
        __syncthreads();
        int cnt = min(128, end - base);
#pragma unroll 2
        for (int j = 0; j < cnt; j++) {
            int s = ssrc[j];
            const float* hp = h + (size_t)s * (H * C) + t;
#pragma unroll
            for (int hh = 0; hh < H; hh++)
                acc[hh] += sw[hh * 128 + j] * hp[hh * C];
        }
        __syncthreads();
    }

#pragma unroll
    for (int hh = 0; hh < H; hh++) red[hh * 128 + t] = den[hh];
    __syncthreads();
    for (int st = 64; st; st >>= 1) {
        if (t < st) {
#pragma unroll
            for (int hh = 0; hh < H; hh++)
                red[hh * 128 + t] += red[hh * 128 + t + st];
        }
        __syncthreads();
    }
#pragma unroll
    for (int hh = 0; hh < H; hh++) {
        float v = acc[hh] / red[hh * 128] + bias[hh * C + t];
        if (doRelu) v = fmaxf(v, 0.f);
        out[(size_t)n * (H * C) + hh * C + t] = v;
    }
}

// ------------------------- launch ---------------------------------------------
extern "C" void kernel_launch(void* const* d_in, const int* in_sizes, int n_in,
                              void* d_out, int out_size) {
    const float* x   = (const float*)d_in[0];
    const int*   ei  = (const int*)d_in[1];
    const float* W1  = (const float*)d_in[2];
    const float* as1 = (const float*)d_in[3];
    const float* ad1 = (const float*)d_in[4];
    const float* b1  = (const float*)d_in[5];
    const float* W2  = (const float*)d_in[6];
    const float* as2 = (const float*)d_in[7];
    const float* ad2 = (const float*)d_in[8];
    const float* b2  = (const float*)d_in[9];
    const float* W3  = (const float*)d_in[10];
    const float* as3 = (const float*)d_in[11];
    const float* ad3 = (const float*)d_in[12];
    const float* b3  = (const float*)d_in[13];
    float* out = (float*)d_out;

    int N = in_sizes[0] / 256;   // 30000
    int E = in_sizes[1] / 2;     // 480000

    cudaFuncSetAttribute(hgemm, cudaFuncAttributeMaxDynamicSharedMemorySize, SMTOT);

    // ---- CSC build ----
    deg_init<<<(N + 255) / 256, 256>>>(N);
    deg_count<<<(E + 255) / 256, 256>>>(ei, E, N);
    scan1024<<<1, 1024>>>(N);
    fill_csc<<<(E + N + 255) / 256, 256>>>(ei, E, N);

    int MT = (N + 127) / 128;  // 235

    // ---- layer 1: K=256 -> 512, relu ----
    split_bf16<<<(N * 256 + 255) / 256, 256>>>(x, 0, N * 256);
    wsplit<<<(256 * 512 + 255) / 256, 256>>>(W1, 256, 512);
    hgemm<<<dim3(4, MT), 256, SMTOT>>>(N, 512, 256);
    attn_coef<<<(N * 4 + 7) / 8, 256>>>(as1, ad1, N, 4);
    aggregate<4><<<N, 128>>>(b1, nullptr, 0, 1);

    // ---- layer 2: K=512 -> 512, relu ----
    split_bf16<<<(N * 512 + 255) / 256, 256>>>(nullptr, 1, N * 512);
    wsplit<<<(512 * 512 + 255) / 256, 256>>>(W2, 512, 512);
    hgemm<<<dim3(4, MT), 256, SMTOT>>>(N, 512, 512);
    attn_coef<<<(N * 4 + 7) / 8, 256>>>(as2, ad2, N, 4);
    aggregate<4><<<N, 128>>>(b2, nullptr, 0, 1);

    // ---- layer 3: K=512 -> 128 (mean over 1 head == identity) ----
    split_bf16<<<(N * 512 + 255) / 256, 256>>>(nullptr, 1, N * 512);
    wsplit<<<(512 * 128 + 255) / 256, 256>>>(W3, 512, 128);
    hgemm<<<dim3(1, MT), 256, SMTOT>>>(N, 128, 512);
    attn_coef<<<(N * 1 + 7) / 8, 256>>>(as3, ad3, N, 1);
    aggregate<1><<<N, 128>>>(b3, out, 1, 0);
}

// round 6
// speedup vs baseline: 1.8450x; 1.3092x over previous
#include <cuda_runtime.h>
#include <cuda_bf16.h>
#include <math.h>
#include <stdint.h>

#define NMAX 30000
#define EMAX 480000
#define TEMAX (EMAX + NMAX)

// ------------------------- device scratch (static; no allocs) ----------------
__device__ __align__(16) float g_h[(size_t)NMAX * 512];
__device__ __align__(16) __nv_bfloat16 g_ah[(size_t)NMAX * 512];
__device__ __align__(16) __nv_bfloat16 g_al[(size_t)NMAX * 512];
__device__ __align__(16) __nv_bfloat16 g_wh[512 * 512];
__device__ __align__(16) __nv_bfloat16 g_wl[512 * 512];
__device__ float g_asrc[NMAX * 4];
__device__ float g_adst[NMAX * 4];
__device__ int   g_deg[NMAX];
__device__ int   g_off[NMAX + 1];
__device__ int   g_cur[NMAX];
__device__ int   g_esrc[TEMAX];

#define SW128(o) ((o) ^ (((o) >> 3) & 0x70))

__device__ __forceinline__ uint32_t smem_u32(const void* p) {
    uint32_t a;
    asm("{ .reg .u64 t; cvta.to.shared.u64 t, %1; cvt.u32.u64 %0, t; }" : "=r"(a) : "l"(p));
    return a;
}
__device__ __forceinline__ void ldm_x4(uint32_t* r, uint32_t addr) {
    asm volatile("ldmatrix.sync.aligned.m8n8.x4.shared.b16 {%0,%1,%2,%3}, [%4];"
                 : "=r"(r[0]), "=r"(r[1]), "=r"(r[2]), "=r"(r[3]) : "r"(addr));
}
__device__ __forceinline__ void mma16816(float* d, const uint32_t* a, const uint32_t* b) {
    asm volatile(
        "mma.sync.aligned.m16n8k16.row.col.f32.bf16.bf16.f32 "
        "{%0,%1,%2,%3}, {%4,%5,%6,%7}, {%8,%9}, {%0,%1,%2,%3};"
        : "+f"(d[0]), "+f"(d[1]), "+f"(d[2]), "+f"(d[3])
        : "r"(a[0]), "r"(a[1]), "r"(a[2]), "r"(a[3]), "r"(b[0]), "r"(b[1]));
}
__device__ __forceinline__ void cp_async16(uint32_t saddr, const void* g, int srcBytes) {
    asm volatile("cp.async.cg.shared.global [%0], [%1], 16, %2;"
                 :: "r"(saddr), "l"(g), "r"(srcBytes) : "memory");
}
#define CP_COMMIT() asm volatile("cp.async.commit_group;" ::: "memory")
#define CP_WAIT(n)  asm volatile("cp.async.wait_group %0;" :: "n"(n) : "memory")

// ------------------------- CSC build ----------------------------------------
__global__ void deg_init(int N) {
    int i = blockIdx.x * blockDim.x + threadIdx.x;
    if (i < N) g_deg[i] = 1;
}
__global__ void deg_count(const int* __restrict__ ei, int E, int N) {
    int i = blockIdx.x * blockDim.x + threadIdx.x;
    if (i < E) {
        int d = ei[E + i];
        if (d >= 0 && d < N) atomicAdd(&g_deg[d], 1);
    }
}
__global__ void scan1024(int N) {
    __shared__ int sp[1024];
    int t = threadIdx.x;
    int IT = (N + 1023) >> 10;
    int b = t * IT, e = min(N, b + IT);
    int s = 0;
    for (int i = b; i < e; i++) s += g_deg[i];
    sp[t] = s;
    __syncthreads();
    for (int off = 1; off < 1024; off <<= 1) {
        int v = (t >= off) ? sp[t - off] : 0;
        __syncthreads();
        sp[t] += v;
        __syncthreads();
    }
    int run = (t == 0) ? 0 : sp[t - 1];
    for (int i = b; i < e; i++) { g_off[i] = run; g_cur[i] = run; run += g_deg[i]; }
    if (t == 1023) g_off[N] = sp[1023];
}
__global__ void fill_csc(const int* __restrict__ ei, int E, int N) {
    int i = blockIdx.x * blockDim.x + threadIdx.x;
    if (i >= E + N) return;
    int s, d;
    if (i < E) { s = ei[i]; d = ei[E + i]; }
    else       { s = i - E; d = s; }
    if (s < 0 || s >= N || d < 0 || d >= N) return;
    int pos = atomicAdd(&g_cur[d], 1);
    if (pos >= 0 && pos < TEMAX) g_esrc[pos] = s;
}

// ------------------------- bf16 split (layer-1 input) / weight transpose -----
__global__ void split_bf16(const float* __restrict__ in, int n) {
    int i = blockIdx.x * blockDim.x + threadIdx.x;
    if (i >= n) return;
    float v = in[i];
    __nv_bfloat16 h = __float2bfloat16(v);
    g_ah[i] = h;
    g_al[i] = __float2bfloat16(v - __bfloat162float(h));
}
__global__ void wsplit(const float* __restrict__ W, int K, int N) {
    int i = blockIdx.x * blockDim.x + threadIdx.x;
    if (i >= K * N) return;
    int k = i / N, n = i - k * N;
    float v = W[i];
    __nv_bfloat16 h = __float2bfloat16(v);
    g_wh[(size_t)n * K + k] = h;
    g_wl[(size_t)n * K + k] = __float2bfloat16(v - __bfloat162float(h));
}

// ------------------------- HMMA bf16-split GEMM + fused attn -----------------
// C[M,N] = A·W, A = g_ah+g_al [M,K] row-major, Wt = g_wh+g_wl [N,K] row-major.
// D = Ah·Bh + Ah·Bl + Al·Bh. CTA tile 128x128 = exactly one head; epilogue also
// computes a_src/a_dst = <h_row, att> for that head (no separate attn kernel).
// 2-stage cp.async pipeline, K-chunk 64. Per-stage: Ah|Al|Bh|Bl @16KB = 64KB.
#define STAGE_B 65536
#define OFF_AH 0
#define OFF_AL 16384
#define OFF_BH 32768
#define OFF_BL 49152
#define SMTOT (2 * STAGE_B)

__global__ __launch_bounds__(256) void hgemm(int M, int N, int K,
                                             const float* __restrict__ at_s,
                                             const float* __restrict__ at_d,
                                             int H) {
    extern __shared__ char smem[];
    uint32_t sb = smem_u32(smem);
    int t = threadIdx.x, lane = t & 31, wid = t >> 5;
    int wm = (wid & 3) * 32;
    int wn = (wid >> 2) * 64;
    int row0 = blockIdx.y * 128, col0 = blockIdx.x * 128;
    int hd = blockIdx.x;  // head index (C==128)

    float acc[2][8][4];
#pragma unroll
    for (int i = 0; i < 2; i++)
#pragma unroll
        for (int j = 0; j < 8; j++)
#pragma unroll
            for (int k = 0; k < 4; k++) acc[i][j][k] = 0.f;

    int q = t & 7;    // 16B quad within 128B row
    int rr = t >> 3;  // 0..31

    int nc = K >> 6;

    // ---- pipelined loads ----
    auto issue = [&](int c) {
        int k0 = c << 6;
        uint32_t stg = sb + (uint32_t)(c & 1) * STAGE_B;
#pragma unroll
        for (int j = 0; j < 4; j++) {
            int r = rr + j * 32;
            uint32_t off = SW128((uint32_t)(r * 128 + q * 16));
            int gr = row0 + r;
            int ok = (gr < M) ? 16 : 0;
            int grc = ok ? gr : (M - 1);
            cp_async16(stg + OFF_AH + off, &g_ah[(size_t)grc * K + k0 + q * 8], ok);
            cp_async16(stg + OFF_AL + off, &g_al[(size_t)grc * K + k0 + q * 8], ok);
            int gn = col0 + r;  // always < N
            cp_async16(stg + OFF_BH + off, &g_wh[(size_t)gn * K + k0 + q * 8], 16);
            cp_async16(stg + OFF_BL + off, &g_wl[(size_t)gn * K + k0 + q * 8], 16);
        }
        CP_COMMIT();
    };

    issue(0);

    for (int c = 0; c < nc; c++) {
        if (c + 1 < nc) {
            issue(c + 1);
            CP_WAIT(1);
        } else {
            CP_WAIT(0);
        }
        __syncthreads();
        uint32_t stg = sb + (uint32_t)(c & 1) * STAGE_B;
#pragma unroll
        for (int ks = 0; ks < 4; ks++) {
            int kc = ks * 16;
            uint32_t ah[2][4], al[2][4];
#pragma unroll
            for (int mt = 0; mt < 2; mt++) {
                int r = wm + mt * 16 + (lane & 15);
                uint32_t off = SW128((uint32_t)(r * 128 + (kc + ((lane >> 4) << 3)) * 2));
                ldm_x4(ah[mt], stg + OFF_AH + off);
                ldm_x4(al[mt], stg + OFF_AL + off);
            }
            uint32_t bh[4][4], bl[4][4];
#pragma unroll
            for (int p = 0; p < 4; p++) {
                int r = wn + p * 16 + ((lane >> 4) << 3) + (lane & 7);
                uint32_t off = SW128((uint32_t)(r * 128 + (kc + ((lane >> 3) & 1) * 8) * 2));
                ldm_x4(bh[p], stg + OFF_BH + off);
                ldm_x4(bl[p], stg + OFF_BL + off);
            }
#pragma unroll
            for (int mt = 0; mt < 2; mt++)
#pragma unroll
                for (int nt = 0; nt < 8; nt++) {
                    const uint32_t* bph = &bh[nt >> 1][(nt & 1) * 2];
                    const uint32_t* bpl = &bl[nt >> 1][(nt & 1) * 2];
                    mma16816(acc[mt][nt], ah[mt], bph);
                    mma16816(acc[mt][nt], ah[mt], bpl);
                    mma16816(acc[mt][nt], al[mt], bph);
                }
        }
        __syncthreads();
    }

    // ---- epilogue: store h (f32) ----
    int g = lane >> 2, cc = (lane & 3) * 2;
#pragma unroll
    for (int mt = 0; mt < 2; mt++) {
        int r0a = row0 + wm + mt * 16 + g;
#pragma unroll
        for (int nt = 0; nt < 8; nt++) {
            int c = col0 + wn + nt * 8 + cc;
            if (r0a < M)
                *(float2*)&g_h[(size_t)r0a * N + c] = make_float2(acc[mt][nt][0], acc[mt][nt][1]);
            if (r0a + 8 < M)
                *(float2*)&g_h[(size_t)(r0a + 8) * N + c] = make_float2(acc[mt][nt][2], acc[mt][nt][3]);
        }
    }

    // ---- fused attention coefficients for this head ----
    // partial dot over this warp's 64 cols, rows (mt, half)
    float ps[2][2] = {{0.f, 0.f}, {0.f, 0.f}};
    float pd[2][2] = {{0.f, 0.f}, {0.f, 0.f}};
    const float* asv = at_s + hd * 128;
    const float* adv = at_d + hd * 128;
#pragma unroll
    for (int nt = 0; nt < 8; nt++) {
        int c = wn + nt * 8 + cc;
        float w0s = asv[c], w1s = asv[c + 1];
        float w0d = adv[c], w1d = adv[c + 1];
#pragma unroll
        for (int mt = 0; mt < 2; mt++) {
            ps[mt][0] += acc[mt][nt][0] * w0s + acc[mt][nt][1] * w1s;
            ps[mt][1] += acc[mt][nt][2] * w0s + acc[mt][nt][3] * w1s;
            pd[mt][0] += acc[mt][nt][0] * w0d + acc[mt][nt][1] * w1d;
            pd[mt][1] += acc[mt][nt][2] * w0d + acc[mt][nt][3] * w1d;
        }
    }
#pragma unroll
    for (int o = 1; o < 4; o <<= 1) {
#pragma unroll
        for (int mt = 0; mt < 2; mt++)
#pragma unroll
            for (int hf = 0; hf < 2; hf++) {
                ps[mt][hf] += __shfl_xor_sync(0xffffffffu, ps[mt][hf], o);
                pd[mt][hf] += __shfl_xor_sync(0xffffffffu, pd[mt][hf], o);
            }
    }
    // smem cross-warp reduce: sred[wnHalf][row][2]
    float* sred = (float*)smem;
    __syncthreads();  // all smem pipeline use done
    if ((lane & 3) == 0) {
#pragma unroll
        for (int mt = 0; mt < 2; mt++)
#pragma unroll
            for (int hf = 0; hf < 2; hf++) {
                int row = wm + mt * 16 + g + hf * 8;
                sred[((wid >> 2) * 128 + row) * 2 + 0] = ps[mt][hf];
                sred[((wid >> 2) * 128 + row) * 2 + 1] = pd[mt][hf];
            }
    }
    __syncthreads();
    if (t < 128) {
        int gr = row0 + t;
        if (gr < M) {
            g_asrc[gr * H + hd] = sred[t * 2 + 0] + sred[(128 + t) * 2 + 0];
            g_adst[gr * H + hd] = sred[t * 2 + 1] + sred[(128 + t) * 2 + 1];
        }
    }
}

// ------------------------- fused softmax + aggregate + bf16 split ------------
// One 128-thread CTA per dst node. Thread t owns channel t of every head.
// writeOut==1: write f32 to outp; else write bf16 hi/lo to g_ah/g_al.
template <int H>
__global__ void aggregate(const float* __restrict__ bias,
                          float* __restrict__ outp, int writeOut, int doRelu) {
    const int C = 128;
    int n = blockIdx.x;
    int t = threadIdx.x;
    __shared__ int   ssrc[128];
    __shared__ float sw[H * 128];
    __shared__ float red[H * 128];

    const float* h = g_h;

    int beg = g_off[n], end = g_off[n + 1];

    float adh[H];
#pragma unroll
    for (int hh = 0; hh < H; hh++) adh[hh] = g_adst[n * H + hh];

    float mx[H];
#pragma unroll
    for (int hh = 0; hh < H; hh++) mx[hh] = -1e30f;
    for (int k = beg + t; k < end; k += 128) {
        int s = g_esrc[k];
#pragma unroll
        for (int hh = 0; hh < H; hh++) {
            float e = g_asrc[s * H + hh] + adh[hh];
            e = e > 0.f ? e : 0.2f * e;
            mx[hh] = fmaxf(mx[hh], e);
        }
    }
#pragma unroll
    for (int hh = 0; hh < H; hh++) red[hh * 128 + t] = mx[hh];
    __syncthreads();
    for (int st = 64; st; st >>= 1) {
        if (t < st) {
#pragma unroll
            for (int hh = 0; hh < H; hh++)
                red[hh * 128 + t] = fmaxf(red[hh * 128 + t], red[hh * 128 + t + st]);
        }
        __syncthreads();
    }
#pragma unroll
    for (int hh = 0; hh < H; hh++) mx[hh] = red[hh * 128];
    __syncthreads();

    float acc[H], den[H];
#pragma unroll
    for (int hh = 0; hh < H; hh++) { acc[hh] = 0.f; den[hh] = 0.f; }

    for (int base = beg; base < end; base += 128) {
        int k = base + t;
        if (k < end) {
            int s = g_esrc[k];
            ssrc[t] = s;
#pragma unroll
            for (int hh = 0; hh < H; hh++) {
                float e = g_asrc[s * H + hh] + adh[hh];
                e = e > 0.f ? e : 0.2f * e;
                float w = expf(e - mx[hh]);
                sw[hh * 128 + t] = w;
                den[hh] += w;
            }
        }
        __syncthreads();
        int cnt = min(128, end - base);
#pragma unroll 2
        for (int j = 0; j < cnt; j++) {
            int s = ssrc[j];
            const float* hp = h + (size_t)s * (H * C) + t;
#pragma unroll
            for (int hh = 0; hh < H; hh++)
                acc[hh] += sw[hh * 128 + j] * hp[hh * C];
        }
        __syncthreads();
    }

#pragma unroll
    for (int hh = 0; hh < H; hh++) red[hh * 128 + t] = den[hh];
    __syncthreads();
    for (int st = 64; st; st >>= 1) {
        if (t < st) {
#pragma unroll
            for (int hh = 0; hh < H; hh++)
                red[hh * 128 + t] += red[hh * 128 + t + st];
        }
        __syncthreads();
    }
#pragma unroll
    for (int hh = 0; hh < H; hh++) {
        float v = acc[hh] / red[hh * 128] + bias[hh * C + t];
        if (doRelu) v = fmaxf(v, 0.f);
        size_t idx = (size_t)n * (H * C) + hh * C + t;
        if (writeOut) {
            outp[idx] = v;
        } else {
            __nv_bfloat16 hi = __float2bfloat16(v);
            g_ah[idx] = hi;
            g_al[idx] = __float2bfloat16(v - __bfloat162float(hi));
        }
    }
}

// ------------------------- launch ---------------------------------------------
extern "C" void kernel_launch(void* const* d_in, const int* in_sizes, int n_in,
                              void* d_out, int out_size) {
    const float* x   = (const float*)d_in[0];
    const int*   ei  = (const int*)d_in[1];
    const float* W1  = (const float*)d_in[2];
    const float* as1 = (const float*)d_in[3];
    const float* ad1 = (const float*)d_in[4];
    const float* b1  = (const float*)d_in[5];
    const float* W2  = (const float*)d_in[6];
    const float* as2 = (const float*)d_in[7];
    const float* ad2 = (const float*)d_in[8];
    const float* b2  = (const float*)d_in[9];
    const float* W3  = (const float*)d_in[10];
    const float* as3 = (const float*)d_in[11];
    const float* ad3 = (const float*)d_in[12];
    const float* b3  = (const float*)d_in[13];
    float* out = (float*)d_out;

    int N = in_sizes[0] / 256;   // 30000
    int E = in_sizes[1] / 2;     // 480000

    cudaFuncSetAttribute(hgemm, cudaFuncAttributeMaxDynamicSharedMemorySize, SMTOT);

    // ---- CSC build ----
    deg_init<<<(N + 255) / 256, 256>>>(N);
    deg_count<<<(E + 255) / 256, 256>>>(ei, E, N);
    scan1024<<<1, 1024>>>(N);
    fill_csc<<<(E + N + 255) / 256, 256>>>(ei, E, N);

    int MT = (N + 127) / 128;  // 235

    // ---- layer 1: K=256 -> 512, relu ----
    split_bf16<<<(N * 256 + 255) / 256, 256>>>(x, N * 256);
    wsplit<<<(256 * 512 + 255) / 256, 256>>>(W1, 256, 512);
    hgemm<<<dim3(4, MT), 256, SMTOT>>>(N, 512, 256, as1, ad1, 4);
    aggregate<4><<<N, 128>>>(b1, nullptr, 0, 1);

    // ---- layer 2: K=512 -> 512, relu ----
    wsplit<<<(512 * 512 + 255) / 256, 256>>>(W2, 512, 512);
    hgemm<<<dim3(4, MT), 256, SMTOT>>>(N, 512, 512, as2, ad2, 4);
    aggregate<4><<<N, 128>>>(b2, nullptr, 0, 1);

    // ---- layer 3: K=512 -> 128 (mean over 1 head == identity) ----
    wsplit<<<(512 * 128 + 255) / 256, 256>>>(W3, 512, 128);
    hgemm<<<dim3(1, MT), 256, SMTOT>>>(N, 128, 512, as3, ad3, 1);
    aggregate<1><<<N, 128>>>(b3, out, 1, 0);
}

// round 7
// speedup vs baseline: 2.2278x; 1.2074x over previous
#include <cuda_runtime.h>
#include <cuda_bf16.h>
#include <math.h>
#include <stdint.h>

#define NMAX 30000
#define EMAX 480000
#define TEMAX (EMAX + NMAX)

// ------------------------- device scratch (static; no allocs) ----------------
__device__ __align__(16) float g_h[(size_t)NMAX * 512];
__device__ __align__(16) __nv_bfloat16 g_ah[(size_t)NMAX * 512];
__device__ __align__(16) __nv_bfloat16 g_al[(size_t)NMAX * 512];
__device__ __align__(16) __nv_bfloat16 g_wh[512 * 512];
__device__ __align__(16) __nv_bfloat16 g_wl[512 * 512];
__device__ __align__(16) float g_asrc[NMAX * 4];
__device__ __align__(16) float g_adst[NMAX * 4];
__device__ int   g_deg[NMAX];
__device__ int   g_off[NMAX + 1];
__device__ int   g_cur[NMAX];
__device__ int   g_esrc[TEMAX];

#define SW128(o) ((o) ^ (((o) >> 3) & 0x70))

__device__ __forceinline__ uint32_t smem_u32(const void* p) {
    uint32_t a;
    asm("{ .reg .u64 t; cvta.to.shared.u64 t, %1; cvt.u32.u64 %0, t; }" : "=r"(a) : "l"(p));
    return a;
}
__device__ __forceinline__ void ldm_x4(uint32_t* r, uint32_t addr) {
    asm volatile("ldmatrix.sync.aligned.m8n8.x4.shared.b16 {%0,%1,%2,%3}, [%4];"
                 : "=r"(r[0]), "=r"(r[1]), "=r"(r[2]), "=r"(r[3]) : "r"(addr));
}
__device__ __forceinline__ void mma16816(float* d, const uint32_t* a, const uint32_t* b) {
    asm volatile(
        "mma.sync.aligned.m16n8k16.row.col.f32.bf16.bf16.f32 "
        "{%0,%1,%2,%3}, {%4,%5,%6,%7}, {%8,%9}, {%0,%1,%2,%3};"
        : "+f"(d[0]), "+f"(d[1]), "+f"(d[2]), "+f"(d[3])
        : "r"(a[0]), "r"(a[1]), "r"(a[2]), "r"(a[3]), "r"(b[0]), "r"(b[1]));
}
__device__ __forceinline__ void cp_async16(uint32_t saddr, const void* g, int srcBytes) {
    asm volatile("cp.async.cg.shared.global [%0], [%1], 16, %2;"
                 :: "r"(saddr), "l"(g), "r"(srcBytes) : "memory");
}
#define CP_COMMIT() asm volatile("cp.async.commit_group;" ::: "memory")
#define CP_WAIT(n)  asm volatile("cp.async.wait_group %0;" :: "n"(n) : "memory")

// ------------------------- CSC build ----------------------------------------
__global__ void deg_init(int N) {
    int i = blockIdx.x * blockDim.x + threadIdx.x;
    if (i < N) g_deg[i] = 1;
}
__global__ void deg_count(const int* __restrict__ ei, int E, int N) {
    int i = blockIdx.x * blockDim.x + threadIdx.x;
    if (i < E) {
        int d = ei[E + i];
        if (d >= 0 && d < N) atomicAdd(&g_deg[d], 1);
    }
}
__global__ void scan1024(int N) {
    __shared__ int sp[1024];
    int t = threadIdx.x;
    int IT = (N + 1023) >> 10;
    int b = t * IT, e = min(N, b + IT);
    int s = 0;
    for (int i = b; i < e; i++) s += g_deg[i];
    sp[t] = s;
    __syncthreads();
    for (int off = 1; off < 1024; off <<= 1) {
        int v = (t >= off) ? sp[t - off] : 0;
        __syncthreads();
        sp[t] += v;
        __syncthreads();
    }
    int run = (t == 0) ? 0 : sp[t - 1];
    for (int i = b; i < e; i++) { g_off[i] = run; g_cur[i] = run; run += g_deg[i]; }
    if (t == 1023) g_off[N] = sp[1023];
}
__global__ void fill_csc(const int* __restrict__ ei, int E, int N) {
    int i = blockIdx.x * blockDim.x + threadIdx.x;
    if (i >= E + N) return;
    int s, d;
    if (i < E) { s = ei[i]; d = ei[E + i]; }
    else       { s = i - E; d = s; }
    if (s < 0 || s >= N || d < 0 || d >= N) return;
    int pos = atomicAdd(&g_cur[d], 1);
    if (pos >= 0 && pos < TEMAX) g_esrc[pos] = s;
}

// ------------------------- bf16 split (layer-1 input) / weight transpose -----
__global__ void split_bf16(const float* __restrict__ in, int n) {
    int i = blockIdx.x * blockDim.x + threadIdx.x;
    if (i >= n) return;
    float v = in[i];
    __nv_bfloat16 h = __float2bfloat16(v);
    g_ah[i] = h;
    g_al[i] = __float2bfloat16(v - __bfloat162float(h));
}
__global__ void wsplit(const float* __restrict__ W, int K, int N) {
    int i = blockIdx.x * blockDim.x + threadIdx.x;
    if (i >= K * N) return;
    int k = i / N, n = i - k * N;
    float v = W[i];
    __nv_bfloat16 h = __float2bfloat16(v);
    g_wh[(size_t)n * K + k] = h;
    g_wl[(size_t)n * K + k] = __float2bfloat16(v - __bfloat162float(h));
}

// ------------------------- HMMA bf16-split GEMM + fused attn -----------------
#define STAGE_B 65536
#define OFF_AH 0
#define OFF_AL 16384
#define OFF_BH 32768
#define OFF_BL 49152
#define SMTOT (2 * STAGE_B)

__global__ __launch_bounds__(256) void hgemm(int M, int N, int K,
                                             const float* __restrict__ at_s,
                                             const float* __restrict__ at_d,
                                             int H) {
    extern __shared__ char smem[];
    uint32_t sb = smem_u32(smem);
    int t = threadIdx.x, lane = t & 31, wid = t >> 5;
    int wm = (wid & 3) * 32;
    int wn = (wid >> 2) * 64;
    int row0 = blockIdx.y * 128, col0 = blockIdx.x * 128;
    int hd = blockIdx.x;

    float acc[2][8][4];
#pragma unroll
    for (int i = 0; i < 2; i++)
#pragma unroll
        for (int j = 0; j < 8; j++)
#pragma unroll
            for (int k = 0; k < 4; k++) acc[i][j][k] = 0.f;

    int q = t & 7;
    int rr = t >> 3;
    int nc = K >> 6;

    auto issue = [&](int c) {
        int k0 = c << 6;
        uint32_t stg = sb + (uint32_t)(c & 1) * STAGE_B;
#pragma unroll
        for (int j = 0; j < 4; j++) {
            int r = rr + j * 32;
            uint32_t off = SW128((uint32_t)(r * 128 + q * 16));
            int gr = row0 + r;
            int ok = (gr < M) ? 16 : 0;
            int grc = ok ? gr : (M - 1);
            cp_async16(stg + OFF_AH + off, &g_ah[(size_t)grc * K + k0 + q * 8], ok);
            cp_async16(stg + OFF_AL + off, &g_al[(size_t)grc * K + k0 + q * 8], ok);
            int gn = col0 + r;
            cp_async16(stg + OFF_BH + off, &g_wh[(size_t)gn * K + k0 + q * 8], 16);
            cp_async16(stg + OFF_BL + off, &g_wl[(size_t)gn * K + k0 + q * 8], 16);
        }
        CP_COMMIT();
    };

    issue(0);

    for (int c = 0; c < nc; c++) {
        if (c + 1 < nc) {
            issue(c + 1);
            CP_WAIT(1);
        } else {
            CP_WAIT(0);
        }
        __syncthreads();
        uint32_t stg = sb + (uint32_t)(c & 1) * STAGE_B;
#pragma unroll
        for (int ks = 0; ks < 4; ks++) {
            int kc = ks * 16;
            uint32_t ah[2][4], al[2][4];
#pragma unroll
            for (int mt = 0; mt < 2; mt++) {
                int r = wm + mt * 16 + (lane & 15);
                uint32_t off = SW128((uint32_t)(r * 128 + (kc + ((lane >> 4) << 3)) * 2));
                ldm_x4(ah[mt], stg + OFF_AH + off);
                ldm_x4(al[mt], stg + OFF_AL + off);
            }
            uint32_t bh[4][4], bl[4][4];
#pragma unroll
            for (int p = 0; p < 4; p++) {
                int r = wn + p * 16 + ((lane >> 4) << 3) + (lane & 7);
                uint32_t off = SW128((uint32_t)(r * 128 + (kc + ((lane >> 3) & 1) * 8) * 2));
                ldm_x4(bh[p], stg + OFF_BH + off);
                ldm_x4(bl[p], stg + OFF_BL + off);
            }
#pragma unroll
            for (int mt = 0; mt < 2; mt++)
#pragma unroll
                for (int nt = 0; nt < 8; nt++) {
                    const uint32_t* bph = &bh[nt >> 1][(nt & 1) * 2];
                    const uint32_t* bpl = &bl[nt >> 1][(nt & 1) * 2];
                    mma16816(acc[mt][nt], ah[mt], bph);
                    mma16816(acc[mt][nt], ah[mt], bpl);
                    mma16816(acc[mt][nt], al[mt], bph);
                }
        }
        __syncthreads();
    }

    // ---- epilogue: store h (f32) ----
    int g = lane >> 2, cc = (lane & 3) * 2;
#pragma unroll
    for (int mt = 0; mt < 2; mt++) {
        int r0a = row0 + wm + mt * 16 + g;
#pragma unroll
        for (int nt = 0; nt < 8; nt++) {
            int c = col0 + wn + nt * 8 + cc;
            if (r0a < M)
                *(float2*)&g_h[(size_t)r0a * N + c] = make_float2(acc[mt][nt][0], acc[mt][nt][1]);
            if (r0a + 8 < M)
                *(float2*)&g_h[(size_t)(r0a + 8) * N + c] = make_float2(acc[mt][nt][2], acc[mt][nt][3]);
        }
    }

    // ---- fused attention coefficients for this head ----
    float ps[2][2] = {{0.f, 0.f}, {0.f, 0.f}};
    float pd[2][2] = {{0.f, 0.f}, {0.f, 0.f}};
    const float* asv = at_s + hd * 128;
    const float* adv = at_d + hd * 128;
#pragma unroll
    for (int nt = 0; nt < 8; nt++) {
        int c = wn + nt * 8 + cc;
        float w0s = asv[c], w1s = asv[c + 1];
        float w0d = adv[c], w1d = adv[c + 1];
#pragma unroll
        for (int mt = 0; mt < 2; mt++) {
            ps[mt][0] += acc[mt][nt][0] * w0s + acc[mt][nt][1] * w1s;
            ps[mt][1] += acc[mt][nt][2] * w0s + acc[mt][nt][3] * w1s;
            pd[mt][0] += acc[mt][nt][0] * w0d + acc[mt][nt][1] * w1d;
            pd[mt][1] += acc[mt][nt][2] * w0d + acc[mt][nt][3] * w1d;
        }
    }
#pragma unroll
    for (int o = 1; o < 4; o <<= 1) {
#pragma unroll
        for (int mt = 0; mt < 2; mt++)
#pragma unroll
            for (int hf = 0; hf < 2; hf++) {
                ps[mt][hf] += __shfl_xor_sync(0xffffffffu, ps[mt][hf], o);
                pd[mt][hf] += __shfl_xor_sync(0xffffffffu, pd[mt][hf], o);
            }
    }
    float* sred = (float*)smem;
    __syncthreads();
    if ((lane & 3) == 0) {
#pragma unroll
        for (int mt = 0; mt < 2; mt++)
#pragma unroll
            for (int hf = 0; hf < 2; hf++) {
                int row = wm + mt * 16 + g + hf * 8;
                sred[((wid >> 2) * 128 + row) * 2 + 0] = ps[mt][hf];
                sred[((wid >> 2) * 128 + row) * 2 + 1] = pd[mt][hf];
            }
    }
    __syncthreads();
    if (t < 128) {
        int gr = row0 + t;
        if (gr < M) {
            g_asrc[gr * H + hd] = sred[t * 2 + 0] + sred[(128 + t) * 2 + 0];
            g_adst[gr * H + hd] = sred[t * 2 + 1] + sred[(128 + t) * 2 + 1];
        }
    }
}

// ------------------------- fused softmax + aggregate + bf16 split ------------
// H=4: thread t owns channels [4t,4t+4) (head = t>>5). One LDG.128 per edge.
// No max pass (exp(e) normalization is exact); per-thread den (no reductions).
__global__ void aggregate4(const float* __restrict__ bias, int doSplit,
                           float* __restrict__ outp) {
    int n = blockIdx.x;
    int t = threadIdx.x;
    int hd = t >> 5;
    __shared__ int   ssrc[128];
    __shared__ float sw[128 * 4];

    int beg = g_off[n], end = g_off[n + 1];

    float4 adh = *(const float4*)&g_adst[n * 4];
    float4 acc = make_float4(0.f, 0.f, 0.f, 0.f);
    float den = 0.f;

    for (int base = beg; base < end; base += 128) {
        int k = base + t;
        if (k < end) {
            int s = g_esrc[k];
            ssrc[t] = s;
            float4 a = *(const float4*)&g_asrc[s * 4];
            float e0 = a.x + adh.x, e1 = a.y + adh.y, e2 = a.z + adh.z, e3 = a.w + adh.w;
            e0 = e0 > 0.f ? e0 : 0.2f * e0;
            e1 = e1 > 0.f ? e1 : 0.2f * e1;
            e2 = e2 > 0.f ? e2 : 0.2f * e2;
            e3 = e3 > 0.f ? e3 : 0.2f * e3;
            float4 w4 = make_float4(__expf(e0), __expf(e1), __expf(e2), __expf(e3));
            *(float4*)&sw[t * 4] = w4;
        }
        __syncthreads();
        int cnt = min(128, end - base);
#pragma unroll 2
        for (int j = 0; j < cnt; j++) {
            int s = ssrc[j];
            float w = sw[j * 4 + hd];
            float4 hv = *(const float4*)&g_h[(size_t)s * 512 + t * 4];
            acc.x += w * hv.x;
            acc.y += w * hv.y;
            acc.z += w * hv.z;
            acc.w += w * hv.w;
            den += w;
        }
        __syncthreads();
    }

    float inv = 1.f / den;
    float4 b4 = *(const float4*)&bias[t * 4];
    float v0 = fmaxf(acc.x * inv + b4.x, 0.f);
    float v1 = fmaxf(acc.y * inv + b4.y, 0.f);
    float v2 = fmaxf(acc.z * inv + b4.z, 0.f);
    float v3 = fmaxf(acc.w * inv + b4.w, 0.f);
    size_t idx = (size_t)n * 512 + t * 4;
    if (doSplit) {
        __nv_bfloat16 h0 = __float2bfloat16(v0), h1 = __float2bfloat16(v1);
        __nv_bfloat16 h2 = __float2bfloat16(v2), h3 = __float2bfloat16(v3);
        __nv_bfloat162 hi01, hi23;
        hi01.x = h0; hi01.y = h1; hi23.x = h2; hi23.y = h3;
        *(__nv_bfloat162*)&g_ah[idx] = hi01;
        *(__nv_bfloat162*)&g_ah[idx + 2] = hi23;
        __nv_bfloat162 lo01, lo23;
        lo01.x = __float2bfloat16(v0 - __bfloat162float(h0));
        lo01.y = __float2bfloat16(v1 - __bfloat162float(h1));
        lo23.x = __float2bfloat16(v2 - __bfloat162float(h2));
        lo23.y = __float2bfloat16(v3 - __bfloat162float(h3));
        *(__nv_bfloat162*)&g_al[idx] = lo01;
        *(__nv_bfloat162*)&g_al[idx + 2] = lo23;
    } else {
        outp[idx] = v0; outp[idx + 1] = v1; outp[idx + 2] = v2; outp[idx + 3] = v3;
    }
}

// H=1, C=128 (layer 3): thread t owns channel t, scalar path, no relu.
__global__ void aggregate1(const float* __restrict__ bias, float* __restrict__ outp) {
    int n = blockIdx.x;
    int t = threadIdx.x;
    __shared__ int   ssrc[128];
    __shared__ float sw[128];

    int beg = g_off[n], end = g_off[n + 1];
    float adh = g_adst[n];
    float acc = 0.f, den = 0.f;

    for (int base = beg; base < end; base += 128) {
        int k = base + t;
        if (k < end) {
            int s = g_esrc[k];
            ssrc[t] = s;
            float e = g_asrc[s] + adh;
            e = e > 0.f ? e : 0.2f * e;
            sw[t] = __expf(e);
        }
        __syncthreads();
        int cnt = min(128, end - base);
#pragma unroll 2
        for (int j = 0; j < cnt; j++) {
            int s = ssrc[j];
            float w = sw[j];
            acc += w * g_h[(size_t)s * 128 + t];
            den += w;
        }
        __syncthreads();
    }
    outp[(size_t)n * 128 + t] = acc / den + bias[t];
}

// ------------------------- launch ---------------------------------------------
extern "C" void kernel_launch(void* const* d_in, const int* in_sizes, int n_in,
                              void* d_out, int out_size) {
    const float* x   = (const float*)d_in[0];
    const int*   ei  = (const int*)d_in[1];
    const float* W1  = (const float*)d_in[2];
    const float* as1 = (const float*)d_in[3];
    const float* ad1 = (const float*)d_in[4];
    const float* b1  = (const float*)d_in[5];
    const float* W2  = (const float*)d_in[6];
    const float* as2 = (const float*)d_in[7];
    const float* ad2 = (const float*)d_in[8];
    const float* b2  = (const float*)d_in[9];
    const float* W3  = (const float*)d_in[10];
    const float* as3 = (const float*)d_in[11];
    const float* ad3 = (const float*)d_in[12];
    const float* b3  = (const float*)d_in[13];
    float* out = (float*)d_out;

    int N = in_sizes[0] / 256;   // 30000
    int E = in_sizes[1] / 2;     // 480000

    cudaFuncSetAttribute(hgemm, cudaFuncAttributeMaxDynamicSharedMemorySize, SMTOT);

    int MT = (N + 127) / 128;  // 235

    // Launch order puts hgemm (layer 1) at captured index for ncu observability.
    split_bf16<<<(N * 256 + 255) / 256, 256>>>(x, N * 256);            // 0
    wsplit<<<(256 * 512 + 255) / 256, 256>>>(W1, 256, 512);            // 1
    deg_init<<<(N + 255) / 256, 256>>>(N);                             // 2
    hgemm<<<dim3(4, MT), 256, SMTOT>>>(N, 512, 256, as1, ad1, 4);      // 3 <- captured
    deg_count<<<(E + 255) / 256, 256>>>(ei, E, N);                     // 4
    scan1024<<<1, 1024>>>(N);                                          // 5
    fill_csc<<<(E + N + 255) / 256, 256>>>(ei, E, N);                  // 6
    aggregate4<<<N, 128>>>(b1, 1, nullptr);                            // 7

    // ---- layer 2 ----
    wsplit<<<(512 * 512 + 255) / 256, 256>>>(W2, 512, 512);
    hgemm<<<dim3(4, MT), 256, SMTOT>>>(N, 512, 512, as2, ad2, 4);
    aggregate4<<<N, 128>>>(b2, 1, nullptr);

    // ---- layer 3 ----
    wsplit<<<(512 * 128 + 255) / 256, 256>>>(W3, 512, 128);
    hgemm<<<dim3(1, MT), 256, SMTOT>>>(N, 128, 512, as3, ad3, 1);
    aggregate1<<<N, 128>>>(b3, out);
}

// round 9
// speedup vs baseline: 2.3360x; 1.0486x over previous
#include <cuda_runtime.h>
#include <cuda_bf16.h>
#include <cuda_fp16.h>
#include <math.h>
#include <stdint.h>

#define NMAX 30000
#define EMAX 480000
#define TEMAX (EMAX + NMAX)

// ------------------------- device scratch (static; no allocs) ----------------
__device__ __align__(16) __half g_hh[(size_t)NMAX * 512];   // GEMM output (fp16)
__device__ __align__(16) __nv_bfloat16 g_ah[(size_t)NMAX * 512];
__device__ __align__(16) __nv_bfloat16 g_al[(size_t)NMAX * 512];
__device__ __align__(16) __nv_bfloat16 g_wh[512 * 512];
__device__ __align__(16) __nv_bfloat16 g_wl[512 * 512];
__device__ __align__(16) float g_asrc[NMAX * 4];
__device__ __align__(16) float g_adst[NMAX * 4];
__device__ int   g_deg[NMAX];
__device__ int   g_off[NMAX + 1];
__device__ int   g_cur[NMAX];
__device__ int   g_esrc[TEMAX];

#define SW128(o) ((o) ^ (((o) >> 3) & 0x70))

__device__ __forceinline__ uint32_t smem_u32(const void* p) {
    uint32_t a;
    asm("{ .reg .u64 t; cvta.to.shared.u64 t, %1; cvt.u32.u64 %0, t; }" : "=r"(a) : "l"(p));
    return a;
}
__device__ __forceinline__ void ldm_x4(uint32_t* r, uint32_t addr) {
    asm volatile("ldmatrix.sync.aligned.m8n8.x4.shared.b16 {%0,%1,%2,%3}, [%4];"
                 : "=r"(r[0]), "=r"(r[1]), "=r"(r[2]), "=r"(r[3]) : "r"(addr));
}
__device__ __forceinline__ void mma16816(float* d, const uint32_t* a, const uint32_t* b) {
    asm volatile(
        "mma.sync.aligned.m16n8k16.row.col.f32.bf16.bf16.f32 "
        "{%0,%1,%2,%3}, {%4,%5,%6,%7}, {%8,%9}, {%0,%1,%2,%3};"
        : "+f"(d[0]), "+f"(d[1]), "+f"(d[2]), "+f"(d[3])
        : "r"(a[0]), "r"(a[1]), "r"(a[2]), "r"(a[3]), "r"(b[0]), "r"(b[1]));
}
__device__ __forceinline__ void cp_async16(uint32_t saddr, const void* g, int srcBytes) {
    asm volatile("cp.async.cg.shared.global [%0], [%1], 16, %2;"
                 :: "r"(saddr), "l"(g), "r"(srcBytes) : "memory");
}
#define CP_COMMIT() asm volatile("cp.async.commit_group;" ::: "memory")
#define CP_WAIT(n)  asm volatile("cp.async.wait_group %0;" :: "n"(n) : "memory")

// ------------------------- CSC build ----------------------------------------
__global__ void deg_init(int N) {
    int i = blockIdx.x * blockDim.x + threadIdx.x;
    if (i < N) g_deg[i] = 1;
}
__global__ void deg_count(const int* __restrict__ ei, int E, int N) {
    int i = blockIdx.x * blockDim.x + threadIdx.x;
    if (i < E) {
        int d = ei[E + i];
        if (d >= 0 && d < N) atomicAdd(&g_deg[d], 1);
    }
}
__global__ void scan1024(int N) {
    __shared__ int sp[1024];
    int t = threadIdx.x;
    int IT = (N + 1023) >> 10;
    int b = t * IT, e = min(N, b + IT);
    int s = 0;
    for (int i = b; i < e; i++) s += g_deg[i];
    sp[t] = s;
    __syncthreads();
    for (int off = 1; off < 1024; off <<= 1) {
        int v = (t >= off) ? sp[t - off] : 0;
        __syncthreads();
        sp[t] += v;
        __syncthreads();
    }
    int run = (t == 0) ? 0 : sp[t - 1];
    for (int i = b; i < e; i++) { g_off[i] = run; g_cur[i] = run; run += g_deg[i]; }
    if (t == 1023) g_off[N] = sp[1023];
}
__global__ void fill_csc(const int* __restrict__ ei, int E, int N) {
    int i = blockIdx.x * blockDim.x + threadIdx.x;
    if (i >= E + N) return;
    int s, d;
    if (i < E) { s = ei[i]; d = ei[E + i]; }
    else       { s = i - E; d = s; }
    if (s < 0 || s >= N || d < 0 || d >= N) return;
    int pos = atomicAdd(&g_cur[d], 1);
    if (pos >= 0 && pos < TEMAX) g_esrc[pos] = s;
}

// ------------------------- bf16 split (layer-1 input) / weight transpose -----
__global__ void split_bf16(const float* __restrict__ in, int n) {
    int i = blockIdx.x * blockDim.x + threadIdx.x;
    if (i >= n) return;
    float v = in[i];
    __nv_bfloat16 h = __float2bfloat16(v);
    g_ah[i] = h;
    g_al[i] = __float2bfloat16(v - __bfloat162float(h));
}
__global__ void wsplit(const float* __restrict__ W, int K, int N) {
    int i = blockIdx.x * blockDim.x + threadIdx.x;
    if (i >= K * N) return;
    int k = i / N, n = i - k * N;
    float v = W[i];
    __nv_bfloat16 h = __float2bfloat16(v);
    g_wh[(size_t)n * K + k] = h;
    g_wl[(size_t)n * K + k] = __float2bfloat16(v - __bfloat162float(h));
}

// ------------------------- HMMA bf16-split GEMM + fused attn -----------------
// 3-stage cp.async pipeline. h stored as fp16.
#define STAGE_B 65536
#define OFF_AH 0
#define OFF_AL 16384
#define OFF_BH 32768
#define OFF_BL 49152
#define SMTOT (3 * STAGE_B)

__global__ __launch_bounds__(256) void hgemm(int M, int N, int K,
                                             const float* __restrict__ at_s,
                                             const float* __restrict__ at_d,
                                             int H) {
    extern __shared__ char smem[];
    uint32_t sb = smem_u32(smem);
    int t = threadIdx.x, lane = t & 31, wid = t >> 5;
    int wm = (wid & 3) * 32;
    int wn = (wid >> 2) * 64;
    int row0 = blockIdx.y * 128, col0 = blockIdx.x * 128;
    int hd = blockIdx.x;

    float acc[2][8][4];
#pragma unroll
    for (int i = 0; i < 2; i++)
#pragma unroll
        for (int j = 0; j < 8; j++)
#pragma unroll
            for (int k = 0; k < 4; k++) acc[i][j][k] = 0.f;

    int q = t & 7;
    int rr = t >> 3;
    int nc = K >> 6;

    auto issue = [&](int c) {
        int k0 = c << 6;
        uint32_t stg = sb + (uint32_t)(c % 3) * STAGE_B;
#pragma unroll
        for (int j = 0; j < 4; j++) {
            int r = rr + j * 32;
            uint32_t off = SW128((uint32_t)(r * 128 + q * 16));
            int gr = row0 + r;
            int ok = (gr < M) ? 16 : 0;
            int grc = ok ? gr : (M - 1);
            cp_async16(stg + OFF_AH + off, &g_ah[(size_t)grc * K + k0 + q * 8], ok);
            cp_async16(stg + OFF_AL + off, &g_al[(size_t)grc * K + k0 + q * 8], ok);
            int gn = col0 + r;
            cp_async16(stg + OFF_BH + off, &g_wh[(size_t)gn * K + k0 + q * 8], 16);
            cp_async16(stg + OFF_BL + off, &g_wl[(size_t)gn * K + k0 + q * 8], 16);
        }
        CP_COMMIT();
    };

    issue(0);
    if (nc > 1) issue(1);

    for (int c = 0; c < nc; c++) {
        if (c + 2 < nc) {
            issue(c + 2);
            CP_WAIT(2);
        } else if (c + 1 < nc) {
            CP_WAIT(1);
        } else {
            CP_WAIT(0);
        }
        __syncthreads();
        uint32_t stg = sb + (uint32_t)(c % 3) * STAGE_B;
#pragma unroll
        for (int ks = 0; ks < 4; ks++) {
            int kc = ks * 16;
            uint32_t ah[2][4], al[2][4];
#pragma unroll
            for (int mt = 0; mt < 2; mt++) {
                int r = wm + mt * 16 + (lane & 15);
                uint32_t off = SW128((uint32_t)(r * 128 + (kc + ((lane >> 4) << 3)) * 2));
                ldm_x4(ah[mt], stg + OFF_AH + off);
                ldm_x4(al[mt], stg + OFF_AL + off);
            }
            uint32_t bh[4][4], bl[4][4];
#pragma unroll
            for (int p = 0; p < 4; p++) {
                int r = wn + p * 16 + ((lane >> 4) << 3) + (lane & 7);
                uint32_t off = SW128((uint32_t)(r * 128 + (kc + ((lane >> 3) & 1) * 8) * 2));
                ldm_x4(bh[p], stg + OFF_BH + off);
                ldm_x4(bl[p], stg + OFF_BL + off);
            }
#pragma unroll
            for (int mt = 0; mt < 2; mt++)
#pragma unroll
                for (int nt = 0; nt < 8; nt++) {
                    const uint32_t* bph = &bh[nt >> 1][(nt & 1) * 2];
                    const uint32_t* bpl = &bl[nt >> 1][(nt & 1) * 2];
                    mma16816(acc[mt][nt], ah[mt], bph);
                    mma16816(acc[mt][nt], ah[mt], bpl);
                    mma16816(acc[mt][nt], al[mt], bph);
                }
        }
        __syncthreads();
    }

    // ---- epilogue: store h (fp16) ----
    int g = lane >> 2, cc = (lane & 3) * 2;
#pragma unroll
    for (int mt = 0; mt < 2; mt++) {
        int r0a = row0 + wm + mt * 16 + g;
#pragma unroll
        for (int nt = 0; nt < 8; nt++) {
            int c = col0 + wn + nt * 8 + cc;
            if (r0a < M)
                *(__half2*)&g_hh[(size_t)r0a * N + c] =
                    __floats2half2_rn(acc[mt][nt][0], acc[mt][nt][1]);
            if (r0a + 8 < M)
                *(__half2*)&g_hh[(size_t)(r0a + 8) * N + c] =
                    __floats2half2_rn(acc[mt][nt][2], acc[mt][nt][3]);
        }
    }

    // ---- fused attention coefficients for this head (from f32 acc) ----
    float ps[2][2] = {{0.f, 0.f}, {0.f, 0.f}};
    float pd[2][2] = {{0.f, 0.f}, {0.f, 0.f}};
    const float* asv = at_s + hd * 128;
    const float* adv = at_d + hd * 128;
#pragma unroll
    for (int nt = 0; nt < 8; nt++) {
        int c = wn + nt * 8 + cc;
        float w0s = asv[c], w1s = asv[c + 1];
        float w0d = adv[c], w1d = adv[c + 1];
#pragma unroll
        for (int mt = 0; mt < 2; mt++) {
            ps[mt][0] += acc[mt][nt][0] * w0s + acc[mt][nt][1] * w1s;
            ps[mt][1] += acc[mt][nt][2] * w0s + acc[mt][nt][3] * w1s;
            pd[mt][0] += acc[mt][nt][0] * w0d + acc[mt][nt][1] * w1d;
            pd[mt][1] += acc[mt][nt][2] * w0d + acc[mt][nt][3] * w1d;
        }
    }
#pragma unroll
    for (int o = 1; o < 4; o <<= 1) {
#pragma unroll
        for (int mt = 0; mt < 2; mt++)
#pragma unroll
            for (int hf = 0; hf < 2; hf++) {
                ps[mt][hf] += __shfl_xor_sync(0xffffffffu, ps[mt][hf], o);
                pd[mt][hf] += __shfl_xor_sync(0xffffffffu, pd[mt][hf], o);
            }
    }
    float* sred = (float*)smem;
    __syncthreads();
    if ((lane & 3) == 0) {
#pragma unroll
        for (int mt = 0; mt < 2; mt++)
#pragma unroll
            for (int hf = 0; hf < 2; hf++) {
                int row = wm + mt * 16 + g + hf * 8;
                sred[((wid >> 2) * 128 + row) * 2 + 0] = ps[mt][hf];
                sred[((wid >> 2) * 128 + row) * 2 + 1] = pd[mt][hf];
            }
    }
    __syncthreads();
    if (t < 128) {
        int gr = row0 + t;
        if (gr < M) {
            g_asrc[gr * H + hd] = sred[t * 2 + 0] + sred[(128 + t) * 2 + 0];
            g_adst[gr * H + hd] = sred[t * 2 + 1] + sred[(128 + t) * 2 + 1];
        }
    }
}

// ------------------------- fused softmax + aggregate + bf16 split ------------
// H=4: thread t owns channels [4t,4t+4) (head = t>>5). One LDG.64 (4 fp16)/edge.
__global__ void aggregate4(const float* __restrict__ bias, int doSplit,
                           float* __restrict__ outp) {
    int n = blockIdx.x;
    int t = threadIdx.x;
    int hd = t >> 5;
    __shared__ int   ssrc[128];
    __shared__ float sw[128 * 4];

    int beg = g_off[n], end = g_off[n + 1];

    float4 adh = *(const float4*)&g_adst[n * 4];
    float4 acc = make_float4(0.f, 0.f, 0.f, 0.f);
    float den = 0.f;

    for (int base = beg; base < end; base += 128) {
        int k = base + t;
        if (k < end) {
            int s = g_esrc[k];
            ssrc[t] = s;
            float4 a = *(const float4*)&g_asrc[s * 4];
            float e0 = a.x + adh.x, e1 = a.y + adh.y, e2 = a.z + adh.z, e3 = a.w + adh.w;
            e0 = e0 > 0.f ? e0 : 0.2f * e0;
            e1 = e1 > 0.f ? e1 : 0.2f * e1;
            e2 = e2 > 0.f ? e2 : 0.2f * e2;
            e3 = e3 > 0.f ? e3 : 0.2f * e3;
            *(float4*)&sw[t * 4] = make_float4(__expf(e0), __expf(e1), __expf(e2), __expf(e3));
        }
        __syncthreads();
        int cnt = min(128, end - base);
#pragma unroll 2
        for (int j = 0; j < cnt; j++) {
            int s = ssrc[j];
            float w = sw[j * 4 + hd];
            uint2 hv = *(const uint2*)&g_hh[(size_t)s * 512 + t * 4];
            float2 f01 = __half22float2(*(__half2*)&hv.x);
            float2 f23 = __half22float2(*(__half2*)&hv.y);
            acc.x += w * f01.x;
            acc.y += w * f01.y;
            acc.z += w * f23.x;
            acc.w += w * f23.y;
            den += w;
        }
        __syncthreads();
    }

    float inv = 1.f / den;
    float4 b4 = *(const float4*)&bias[t * 4];
    float v0 = fmaxf(acc.x * inv + b4.x, 0.f);
    float v1 = fmaxf(acc.y * inv + b4.y, 0.f);
    float v2 = fmaxf(acc.z * inv + b4.z, 0.f);
    float v3 = fmaxf(acc.w * inv + b4.w, 0.f);
    size_t idx = (size_t)n * 512 + t * 4;
    if (doSplit) {
        __nv_bfloat16 h0 = __float2bfloat16(v0), h1 = __float2bfloat16(v1);
        __nv_bfloat16 h2 = __float2bfloat16(v2), h3 = __float2bfloat16(v3);
        __nv_bfloat162 hi01, hi23;
        hi01.x = h0; hi01.y = h1; hi23.x = h2; hi23.y = h3;
        *(__nv_bfloat162*)&g_ah[idx] = hi01;
        *(__nv_bfloat162*)&g_ah[idx + 2] = hi23;
        __nv_bfloat162 lo01, lo23;
        lo01.x = __float2bfloat16(v0 - __bfloat162float(h0));
        lo01.y = __float2bfloat16(v1 - __bfloat162float(h1));
        lo23.x = __float2bfloat16(v2 - __bfloat162float(h2));
        lo23.y = __float2bfloat16(v3 - __bfloat162float(h3));
        *(__nv_bfloat162*)&g_al[idx] = lo01;
        *(__nv_bfloat162*)&g_al[idx + 2] = lo23;
    } else {
        outp[idx] = v0; outp[idx + 1] = v1; outp[idx + 2] = v2; outp[idx + 3] = v3;
    }
}

// H=1, C=128 (layer 3): thread t owns channel t, no relu.
__global__ void aggregate1(const float* __restrict__ bias, float* __restrict__ outp) {
    int n = blockIdx.x;
    int t = threadIdx.x;
    __shared__ int   ssrc[128];
    __shared__ float sw[128];

    int beg = g_off[n], end = g_off[n + 1];
    float adh = g_adst[n];
    float acc = 0.f, den = 0.f;

    for (int base = beg; base < end; base += 128) {
        int k = base + t;
        if (k < end) {
            int s = g_esrc[k];
            ssrc[t] = s;
            float e = g_asrc[s] + adh;
            e = e > 0.f ? e : 0.2f * e;
            sw[t] = __expf(e);
        }
        __syncthreads();
        int cnt = min(128, end - base);
#pragma unroll 2
        for (int j = 0; j < cnt; j++) {
            int s = ssrc[j];
            float w = sw[j];
            acc += w * __half2float(g_hh[(size_t)s * 128 + t]);
            den += w;
        }
        __syncthreads();
    }
    outp[(size_t)n * 128 + t] = acc / den + bias[t];
}

// ------------------------- launch ---------------------------------------------
extern "C" void kernel_launch(void* const* d_in, const int* in_sizes, int n_in,
                              void* d_out, int out_size) {
    const float* x   = (const float*)d_in[0];
    const int*   ei  = (const int*)d_in[1];
    const float* W1  = (const float*)d_in[2];
    const float* as1 = (const float*)d_in[3];
    const float* ad1 = (const float*)d_in[4];
    const float* b1  = (const float*)d_in[5];
    const float* W2  = (const float*)d_in[6];
    const float* as2 = (const float*)d_in[7];
    const float* ad2 = (const float*)d_in[8];
    const float* b2  = (const float*)d_in[9];
    const float* W3  = (const float*)d_in[10];
    const float* as3 = (const float*)d_in[11];
    const float* ad3 = (const float*)d_in[12];
    const float* b3  = (const float*)d_in[13];
    float* out = (float*)d_out;

    int N = in_sizes[0] / 256;   // 30000
    int E = in_sizes[1] / 2;     // 480000

    cudaFuncSetAttribute(hgemm, cudaFuncAttributeMaxDynamicSharedMemorySize, SMTOT);

    int MT = (N + 127) / 128;  // 235

    split_bf16<<<(N * 256 + 255) / 256, 256>>>(x, N * 256);            // 0
    wsplit<<<(256 * 512 + 255) / 256, 256>>>(W1, 256, 512);            // 1
    deg_init<<<(N + 255) / 256, 256>>>(N);                             // 2
    hgemm<<<dim3(4, MT), 256, SMTOT>>>(N, 512, 256, as1, ad1, 4);      // 3 <- captured
    deg_count<<<(E + 255) / 256, 256>>>(ei, E, N);                     // 4
    scan1024<<<1, 1024>>>(N);                                          // 5
    fill_csc<<<(E + N + 255) / 256, 256>>>(ei, E, N);                  // 6
    aggregate4<<<N, 128>>>(b1, 1, nullptr);                            // 7

    // ---- layer 2 ----
    wsplit<<<(512 * 512 + 255) / 256, 256>>>(W2, 512, 512);
    hgemm<<<dim3(4, MT), 256, SMTOT>>>(N, 512, 512, as2, ad2, 4);
    aggregate4<<<N, 128>>>(b2, 1, nullptr);

    // ---- layer 3 ----
    wsplit<<<(512 * 128 + 255) / 256, 256>>>(W3, 512, 128);
    hgemm<<<dim3(1, MT), 256, SMTOT>>>(N, 128, 512, as3, ad3, 1);
    aggregate1<<<N, 128>>>(b3, out);
}